// round 12
// baseline (speedup 1.0000x reference)
#include <cuda_runtime.h>
#include <cuda_bf16.h>
#include <cstddef>
#include <cstdint>

#define Bsz 64
#define Sq  512
#define Isz 512
#define Hsz 1024
#define G3  3072   // 3*Hsz

// Scratch (static device allocations; no cudaMalloc anywhere)
__device__ float g_xg[(size_t)Sq * Bsz * G3];              // x_gates [s][b][g]
__device__ __nv_bfloat16 g_hb[3][2][Bsz * Hsz];            // h ring-3 [ring][hi/lo][b][j]
__device__ __nv_bfloat16 g_Ahi[(size_t)Bsz * Sq * Isz];    // inputs hi  [m][k]
__device__ __nv_bfloat16 g_Alo[(size_t)Bsz * Sq * Isz];    // inputs lo
__device__ __nv_bfloat16 g_Whi[(size_t)G3 * Isz];          // Wih hi [n][k]
__device__ __nv_bfloat16 g_Wlo[(size_t)G3 * Isz];          // Wih lo
__device__ int g_flags[Sq][8];                             // per-(step,window) producer counters

// ---------------------------------------------------------------------------
// helpers
// ---------------------------------------------------------------------------
__device__ __forceinline__ uint32_t smem_u32(const void* p) {
    uint32_t a;
    asm("{ .reg .u64 t; cvta.to.shared.u64 t, %1; cvt.u32.u64 %0, t; }"
        : "=r"(a) : "l"(p));
    return a;
}
__device__ __forceinline__ void cpa16(uint32_t sdst, const void* gp) {
    asm volatile("cp.async.cg.shared.global [%0], [%1], 16;\n"
                 :: "r"(sdst), "l"(gp) : "memory");
}
__device__ __forceinline__ void ldm4(uint32_t& r0, uint32_t& r1,
                                     uint32_t& r2, uint32_t& r3, uint32_t addr) {
    asm volatile("ldmatrix.sync.aligned.m8n8.x4.shared.b16 {%0,%1,%2,%3}, [%4];"
                 : "=r"(r0), "=r"(r1), "=r"(r2), "=r"(r3) : "r"(addr));
}
__device__ __forceinline__ void mma_bf16(float& d0, float& d1, float& d2, float& d3,
                                         uint32_t a0, uint32_t a1, uint32_t a2, uint32_t a3,
                                         uint32_t b0, uint32_t b1) {
    asm volatile(
        "mma.sync.aligned.m16n8k16.row.col.f32.bf16.bf16.f32 "
        "{%0,%1,%2,%3}, {%4,%5,%6,%7}, {%8,%9}, {%0,%1,%2,%3};"
        : "+f"(d0), "+f"(d1), "+f"(d2), "+f"(d3)
        : "r"(a0), "r"(a1), "r"(a2), "r"(a3), "r"(b0), "r"(b1));
}
// ALL lanes spin with an ACQUIRE load until *f >= target (bounded: fail loud)
__device__ __forceinline__ void wait_flag_acq(const int* f, int target) {
    int v = 0;
    #pragma unroll 1
    for (long i = 0; i < 100000000L; i++) {
        asm volatile("ld.acquire.gpu.global.s32 %0, [%1];"
                     : "=r"(v) : "l"(f) : "memory");
        if (v >= target) break;
    }
    __syncwarp();
}
// RELEASE increment of a flag
__device__ __forceinline__ void flag_release_add(int* f) {
    asm volatile("red.release.gpu.global.add.s32 [%0], %1;"
                 :: "l"(f), "r"(1) : "memory");
}

// ---------------------------------------------------------------------------
// fp32 -> bf16 hi/lo split (vectorized, once)
// ---------------------------------------------------------------------------
__global__ void split_kernel(const float* __restrict__ src,
                             __nv_bfloat16* __restrict__ hi,
                             __nv_bfloat16* __restrict__ lo)
{
    size_t i = (size_t)blockIdx.x * blockDim.x + threadIdx.x;   // float4 index
    float4 v = ((const float4*)src)[i];
    float f[4] = {v.x, v.y, v.z, v.w};
    __nv_bfloat16 h[4], l[4];
    #pragma unroll
    for (int q = 0; q < 4; q++) {
        h[q] = __float2bfloat16(f[q]);
        l[q] = __float2bfloat16(f[q] - __bfloat162float(h[q]));
    }
    ((uint2*)hi)[i] = *(uint2*)h;
    ((uint2*)lo)[i] = *(uint2*)l;
}

// h0 fp32 [b][j] -> bf16 hi/lo into ring buffer 0
__global__ void h0_prep_kernel(const float* __restrict__ h0,
                               __nv_bfloat16* __restrict__ hhi,
                               __nv_bfloat16* __restrict__ hlo)
{
    int idx = blockIdx.x * blockDim.x + threadIdx.x;
    float v = h0[idx];
    __nv_bfloat16 hi = __float2bfloat16(v);
    hhi[idx] = hi;
    hlo[idx] = __float2bfloat16(v - __bfloat162float(hi));
}

// ---------------------------------------------------------------------------
// Kernel 1: x_gates = inputs @ W_ih^T + bias_ih on tensor cores (proven R10)
// ---------------------------------------------------------------------------
#define XROWB 80u
#define XHALF (128u * XROWB)
#define XBUF  (4u * XHALF)
#define XGEMM_SMEM (2u * XBUF)

extern __shared__ char xsmem[];

__global__ __launch_bounds__(256) void xgemm_mma_kernel(
    const __nv_bfloat16* __restrict__ Ahi,
    const __nv_bfloat16* __restrict__ Alo,
    const __nv_bfloat16* __restrict__ Whi,
    const __nv_bfloat16* __restrict__ Wlo,
    const float* __restrict__ bias,
    float* __restrict__ xg)
{
    const uint32_t sb = smem_u32(xsmem);
    const int t    = threadIdx.x;
    const int wid  = t >> 5;
    const int lane = t & 31;
    const int m0   = blockIdx.y * 128;
    const int n0   = blockIdx.x * 128;
    const int wm   = (wid >> 2) * 64;
    const int wn   = (wid & 3) * 32;

    const int sub = lane >> 3;
    const uint32_t a_lane_off =
        (uint32_t)(((lane & 7) + ((sub & 1) << 3)) * XROWB + ((sub >> 1) << 4));
    const int bg   = lane >> 2;
    const int btid = lane & 3;

    float acc[4][4][4] = {};

    auto stage = [&](int w, int buf) {
        #pragma unroll
        for (int i = 0; i < 8; i++) {
            int c   = t + 256 * i;
            int op  = c >> 9;
            int rem = c & 511;
            int row = rem >> 2;
            int q   = rem & 3;
            const __nv_bfloat16* src;
            if (op == 0)      src = Ahi + (size_t)(m0 + row) * Isz + w * 32 + q * 8;
            else if (op == 1) src = Alo + (size_t)(m0 + row) * Isz + w * 32 + q * 8;
            else if (op == 2) src = Whi + (size_t)(n0 + row) * Isz + w * 32 + q * 8;
            else              src = Wlo + (size_t)(n0 + row) * Isz + w * 32 + q * 8;
            cpa16(sb + (uint32_t)buf * XBUF + (uint32_t)op * XHALF
                     + (uint32_t)(row * XROWB + q * 16), src);
        }
        asm volatile("cp.async.commit_group;\n" ::: "memory");
    };

    stage(0, 0);

    #pragma unroll 1
    for (int w = 0; w < 16; w++) {
        if (w < 15) {
            stage(w + 1, (w + 1) & 1);
            asm volatile("cp.async.wait_group 1;\n" ::: "memory");
        } else {
            asm volatile("cp.async.wait_group 0;\n" ::: "memory");
        }
        __syncthreads();

        const uint32_t bufb = sb + (uint32_t)(w & 1) * XBUF;
        const uint32_t* bhi_row[4];
        const uint32_t* blo_row[4];
        #pragma unroll
        for (int ni = 0; ni < 4; ni++) {
            uint32_t r = (uint32_t)((wn + ni * 8 + bg) * XROWB);
            bhi_row[ni] = (const uint32_t*)(xsmem + (w & 1) * XBUF + 2 * XHALF + r);
            blo_row[ni] = (const uint32_t*)(xsmem + (w & 1) * XBUF + 3 * XHALF + r);
        }

        #pragma unroll
        for (int kt = 0; kt < 2; kt++) {
            uint32_t bh0[4], bh1[4], bl0[4], bl1[4];
            #pragma unroll
            for (int ni = 0; ni < 4; ni++) {
                int kw = kt * 8 + btid;
                bh0[ni] = bhi_row[ni][kw];
                bh1[ni] = bhi_row[ni][kw + 4];
                bl0[ni] = blo_row[ni][kw];
                bl1[ni] = blo_row[ni][kw + 4];
            }
            #pragma unroll
            for (int mi = 0; mi < 4; mi++) {
                uint32_t abase = bufb + a_lane_off
                               + (uint32_t)((wm + mi * 16) * XROWB + kt * 32);
                uint32_t ah0, ah1, ah2, ah3, al0, al1, al2, al3;
                ldm4(ah0, ah1, ah2, ah3, abase);
                ldm4(al0, al1, al2, al3, abase + XHALF);
                #pragma unroll
                for (int ni = 0; ni < 4; ni++) {
                    float* d = acc[mi][ni];
                    mma_bf16(d[0], d[1], d[2], d[3], ah0, ah1, ah2, ah3, bh0[ni], bh1[ni]);
                    mma_bf16(d[0], d[1], d[2], d[3], ah0, ah1, ah2, ah3, bl0[ni], bl1[ni]);
                    mma_bf16(d[0], d[1], d[2], d[3], al0, al1, al2, al3, bh0[ni], bh1[ni]);
                }
            }
        }
        __syncthreads();
    }

    #pragma unroll
    for (int ni = 0; ni < 4; ni++) {
        int nn = n0 + wn + ni * 8 + 2 * (lane & 3);
        float b0 = bias[nn], b1 = bias[nn + 1];
        #pragma unroll
        for (int mi = 0; mi < 4; mi++) {
            const float* d = acc[mi][ni];
            int m = m0 + wm + mi * 16 + (lane >> 2);
            int s = m & (Sq - 1), b = m >> 9;
            *(float2*)(xg + (size_t)s * (Bsz * G3) + (size_t)b * G3 + nn) =
                make_float2(d[0] + b0, d[1] + b1);
            int m2 = m + 8;
            int s2 = m2 & (Sq - 1), b2 = m2 >> 9;
            *(float2*)(xg + (size_t)s2 * (Bsz * G3) + (size_t)b2 * G3 + nn) =
                make_float2(d[2] + b0, d[3] + b1);
        }
    }
}

// ---------------------------------------------------------------------------
// Kernel 2: PERSISTENT bf16-split mma.sync GRU scan, per-window flags with
// formal acquire/release ordering + 3-deep h ring.
//   producer: writers __stcg + __threadfence, bar.sync, t0 red.release(+1)
//   consumer: all lanes ld.acquire spin before staging window w of step s
// ---------------------------------------------------------------------------
#define OFF_D   0u
#define OFF_W   8192u
#define WROWB   2064u
#define OFF_WLO (OFF_W + 24u * WROWB)
#define OFF_H   107520u
#define HROWB   272u
#define HHALF   (64u * HROWB)
#define HBUF    (2u * HHALF)
#define SCAN_SMEM (OFF_H + 2u * HBUF)

extern __shared__ char smem_raw[];

__global__ __launch_bounds__(512, 1) void gru_scan_kernel(
    const float* __restrict__ xg,
    const float* __restrict__ Whh,
    const float* __restrict__ bhh,
    __nv_bfloat16* __restrict__ hb,     // g_hb base: [3][2][B*H]
    float* __restrict__ out)
{
    const uint32_t sb = smem_u32(smem_raw);
    const int t    = threadIdx.x;
    const int wid  = t >> 5;
    const int lane = t & 31;
    const int j0   = blockIdx.x * 8;
    const int wown = blockIdx.x >> 4;          // k-window this block produces

    // ---- W -> smem as bf16 hi/lo (once) ----
    #pragma unroll
    for (int i = 0; i < 48; i++) {
        int idx = t + 512 * i;
        int r = idx >> 10;
        int k = idx & 1023;
        int gate = r >> 3, jr = r & 7;
        float v = Whh[(size_t)(gate * Hsz + j0 + jr) * Hsz + k];
        __nv_bfloat16 hi = __float2bfloat16(v);
        __nv_bfloat16 lo = __float2bfloat16(v - __bfloat162float(hi));
        *(__nv_bfloat16*)(smem_raw + OFF_W   + r * WROWB + k * 2) = hi;
        *(__nv_bfloat16*)(smem_raw + OFF_WLO + r * WROWB + k * 2) = lo;
    }
    __syncthreads();

    const int nt = wid >> 2;
    const int mt = wid & 3;
    const int sub   = lane >> 3;
    const int a_row = mt * 16 + (lane & 7) + ((sub & 1) << 3);
    const uint32_t a_off = (uint32_t)(a_row * HROWB + ((sub >> 1) << 4));
    const int bg   = lane >> 2;
    const int btid = lane & 3;
    const uint32_t* whi_p = (const uint32_t*)(smem_raw + OFF_W   + (nt * 8 + bg) * WROWB);
    const uint32_t* wlo_p = (const uint32_t*)(smem_raw + OFF_WLO + (nt * 8 + bg) * WROWB);

    float bhr[8], bhz[8], bhn[8];
    if (t < 64) {
        #pragma unroll
        for (int jj = 0; jj < 8; jj++) {
            bhr[jj] = bhh[j0 + jj];
            bhz[jj] = bhh[Hsz + j0 + jj];
            bhn[jj] = bhh[2 * Hsz + j0 + jj];
        }
    }

    float* Dp = (float*)(smem_raw + OFF_D);

    for (int s = 0; s < Sq; s++) {
        const int rin  = s % 3, rout = (s + 1) % 3;
        const __nv_bfloat16* hin_hi = hb + (size_t)rin * 2 * (Bsz * Hsz);
        const __nv_bfloat16* hin_lo = hin_hi + (Bsz * Hsz);
        __nv_bfloat16* hout_hi = hb + (size_t)rout * 2 * (Bsz * Hsz);
        __nv_bfloat16* hout_lo = hout_hi + (Bsz * Hsz);
        const float* xgs = xg + (size_t)s * (Bsz * G3);

        float xr[8], xz[8], xn[8], hp[8];
        if (t < 64) {
            const float* xb = xgs + (size_t)t * G3 + j0;
            float4 v0 = __ldg((const float4*)xb);
            float4 v1 = __ldg((const float4*)(xb + 4));
            xr[0]=v0.x; xr[1]=v0.y; xr[2]=v0.z; xr[3]=v0.w;
            xr[4]=v1.x; xr[5]=v1.y; xr[6]=v1.z; xr[7]=v1.w;
            v0 = __ldg((const float4*)(xb + Hsz));
            v1 = __ldg((const float4*)(xb + Hsz + 4));
            xz[0]=v0.x; xz[1]=v0.y; xz[2]=v0.z; xz[3]=v0.w;
            xz[4]=v1.x; xz[5]=v1.y; xz[6]=v1.z; xz[7]=v1.w;
            v0 = __ldg((const float4*)(xb + 2 * Hsz));
            v1 = __ldg((const float4*)(xb + 2 * Hsz + 4));
            xn[0]=v0.x; xn[1]=v0.y; xn[2]=v0.z; xn[3]=v0.w;
            xn[4]=v1.x; xn[5]=v1.y; xn[6]=v1.z; xn[7]=v1.w;
            // h_prev slice (t, j0..j0+8): produced by THIS block last step
            uint4 uh = __ldcg((const uint4*)(hin_hi + (size_t)t * Hsz + j0));
            uint4 ul = __ldcg((const uint4*)(hin_lo + (size_t)t * Hsz + j0));
            const __nv_bfloat16* ph = (const __nv_bfloat16*)&uh;
            const __nv_bfloat16* pl = (const __nv_bfloat16*)&ul;
            #pragma unroll
            for (int jj = 0; jj < 8; jj++)
                hp[jj] = __bfloat162float(ph[jj]) + __bfloat162float(pl[jj]);
        }

        float dA[4] = {}, dB[4] = {};

        auto stage = [&](int w) {
            if (s > 0) wait_flag_acq(&g_flags[s][w], 16);   // h[s] window w ready
            int buf = w & 1;
            #pragma unroll
            for (int i = 0; i < 4; i++) {
                int c    = t + 512 * i;
                int half = c >> 10;
                int rem  = c & 1023;
                int row  = rem >> 4;
                int cq   = rem & 15;
                const char* src = (const char*)(half ? hin_lo : hin_hi)
                                  + row * 2048 + w * 256 + cq * 16;
                cpa16(sb + OFF_H + buf * HBUF + half * HHALF
                         + row * HROWB + cq * 16, src);
            }
            asm volatile("cp.async.commit_group;\n" ::: "memory");
        };

        stage(0);

        #pragma unroll 1
        for (int w = 0; w < 8; w++) {
            if (w < 7) {
                stage(w + 1);
                asm volatile("cp.async.wait_group 1;\n" ::: "memory");
            } else {
                asm volatile("cp.async.wait_group 0;\n" ::: "memory");
            }
            __syncthreads();

            if (wid < 12) {
                const uint32_t abase = sb + OFF_H + (uint32_t)(w & 1) * HBUF + a_off;
                #pragma unroll
                for (int kt = 0; kt < 8; kt++) {
                    float* d = (kt & 1) ? dB : dA;
                    uint32_t ah0, ah1, ah2, ah3, al0, al1, al2, al3;
                    ldm4(ah0, ah1, ah2, ah3, abase + kt * 32);
                    ldm4(al0, al1, al2, al3, abase + HHALF + kt * 32);
                    int kw = (w * 8 + kt) * 8 + btid;
                    uint32_t bh0 = whi_p[kw], bh1 = whi_p[kw + 4];
                    uint32_t bl0 = wlo_p[kw], bl1 = wlo_p[kw + 4];
                    mma_bf16(d[0], d[1], d[2], d[3], ah0, ah1, ah2, ah3, bh0, bh1);
                    mma_bf16(d[0], d[1], d[2], d[3], ah0, ah1, ah2, ah3, bl0, bl1);
                    mma_bf16(d[0], d[1], d[2], d[3], al0, al1, al2, al3, bh0, bh1);
                }
            }
            __syncthreads();
        }

        if (wid < 12) {
            int m  = mt * 16 + (lane >> 2);
            int nc = nt * 8 + 2 * (lane & 3);
            Dp[m * 26 + nc]           = dA[0] + dB[0];
            Dp[m * 26 + nc + 1]       = dA[1] + dB[1];
            Dp[(m + 8) * 26 + nc]     = dA[2] + dB[2];
            Dp[(m + 8) * 26 + nc + 1] = dA[3] + dB[3];
        }
        __syncthreads();

        if (t < 64) {
            __nv_bfloat16 whi[8], wlo[8];
            float hnv[8];
            #pragma unroll
            for (int jj = 0; jj < 8; jj++) {
                float ar = Dp[t * 26 + jj];
                float az = Dp[t * 26 + 8 + jj];
                float an = Dp[t * 26 + 16 + jj];
                float r = 1.f / (1.f + expf(-(xr[jj] + ar + bhr[jj])));
                float z = 1.f / (1.f + expf(-(xz[jj] + az + bhz[jj])));
                float n = tanhf(xn[jj] + r * (an + bhn[jj]));
                float h = (1.f - z) * n + z * hp[jj];
                hnv[jj] = h;
                __nv_bfloat16 hi = __float2bfloat16(h);
                whi[jj] = hi;
                wlo[jj] = __float2bfloat16(h - __bfloat162float(hi));
            }
            float* op = out + (size_t)t * Sq * Hsz + (size_t)s * Hsz + j0;
            *(float4*)op       = make_float4(hnv[0], hnv[1], hnv[2], hnv[3]);
            *(float4*)(op + 4) = make_float4(hnv[4], hnv[5], hnv[6], hnv[7]);
            // h' straight to L2 (no L1 between store and release)
            __stcg((uint4*)(hout_hi + (size_t)t * Hsz + j0), *(uint4*)whi);
            __stcg((uint4*)(hout_lo + (size_t)t * Hsz + j0), *(uint4*)wlo);
            if (s == Sq - 1) {
                float* hn = out + (size_t)Bsz * Sq * Hsz + (size_t)t * Hsz + j0;
                *(float4*)hn       = make_float4(hnv[0], hnv[1], hnv[2], hnv[3]);
                *(float4*)(hn + 4) = make_float4(hnv[4], hnv[5], hnv[6], hnv[7]);
            }
            __threadfence();   // writers' release fence (R10-proven chain)
        }

        __syncthreads();
        // publish with RELEASE semantics: this block's slice of h[s+1] ready
        if (t == 0 && s + 1 < Sq)
            flag_release_add(&g_flags[s + 1][wown]);
        __syncthreads();
    }
}

// ---------------------------------------------------------------------------
// kernel_launch (graph-capturable: kernels + one async memset)
// ---------------------------------------------------------------------------
extern "C" void kernel_launch(void* const* d_in, const int* in_sizes, int n_in,
                              void* d_out, int out_size)
{
    const float* inputs = (const float*)d_in[0];
    const float* h0     = (const float*)d_in[1];
    const float* Wih    = (const float*)d_in[2];
    const float* Whh    = (const float*)d_in[3];
    const float* bih    = (const float*)d_in[4];
    const float* bhh    = (const float*)d_in[5];
    float* out = (float*)d_out;

    float* xg = nullptr;
    __nv_bfloat16 *hb = nullptr, *ahi = nullptr, *alo = nullptr,
                  *whi = nullptr, *wlo = nullptr;
    int* flags = nullptr;
    cudaGetSymbolAddress((void**)&xg,  g_xg);
    cudaGetSymbolAddress((void**)&hb,  g_hb);
    cudaGetSymbolAddress((void**)&ahi, g_Ahi);
    cudaGetSymbolAddress((void**)&alo, g_Alo);
    cudaGetSymbolAddress((void**)&whi, g_Whi);
    cudaGetSymbolAddress((void**)&wlo, g_Wlo);
    cudaGetSymbolAddress((void**)&flags, g_flags);

    cudaFuncSetAttribute(gru_scan_kernel,
                         cudaFuncAttributeMaxDynamicSharedMemorySize, SCAN_SMEM);
    cudaFuncSetAttribute(xgemm_mma_kernel,
                         cudaFuncAttributeMaxDynamicSharedMemorySize, XGEMM_SMEM);

    // zero the producer flags for this run (capturable memset node)
    cudaMemsetAsync(flags, 0, (size_t)Sq * 8 * sizeof(int));

    // Phase A: split inputs/Wih to bf16 hi/lo, then HMMA input-projection GEMM
    split_kernel<<<(int)((size_t)Bsz * Sq * Isz / 4 / 256), 256>>>(inputs, ahi, alo);
    split_kernel<<<(int)((size_t)G3 * Isz / 4 / 256), 256>>>(Wih, whi, wlo);
    h0_prep_kernel<<<(Bsz * Hsz) / 256, 256>>>(h0, hb, hb + Bsz * Hsz);

    dim3 ggrid(G3 / 128, (Bsz * Sq) / 128);   // (24, 256)
    xgemm_mma_kernel<<<ggrid, 256, XGEMM_SMEM>>>(ahi, alo, whi, wlo, bih, xg);

    // Phase B: whole scan in ONE persistent kernel with per-window flags
    gru_scan_kernel<<<128, 512, SCAN_SMEM>>>(xg, Whh, bhh, hb, out);
}

// round 13
// speedup vs baseline: 1.0735x; 1.0735x over previous
#include <cuda_runtime.h>
#include <cuda_bf16.h>
#include <cstddef>
#include <cstdint>

#define Bsz 64
#define Sq  512
#define Isz 512
#define Hsz 1024
#define G3  3072   // 3*Hsz

// Scratch (static device allocations; no cudaMalloc anywhere)
__device__ float g_xg[(size_t)Sq * Bsz * G3];              // x_gates [s][b][g]
__device__ __nv_bfloat16 g_hb[2][2][Bsz * Hsz];            // h ping-pong [ping][hi/lo][b][j]
__device__ __nv_bfloat16 g_Ahi[(size_t)Bsz * Sq * Isz];    // inputs hi  [m][k]
__device__ __nv_bfloat16 g_Alo[(size_t)Bsz * Sq * Isz];    // inputs lo
__device__ __nv_bfloat16 g_Whi[(size_t)G3 * Isz];          // Wih hi [n][k]
__device__ __nv_bfloat16 g_Wlo[(size_t)G3 * Isz];          // Wih lo

// two-level grid barrier (monotonic counters: no reset, graph-replay safe)
struct PadCtr { unsigned v; unsigned pad[31]; };
__device__ PadCtr  g_sub[8];        // 16 arrivals each per step
__device__ unsigned g_root;         // 8 arrivals per step
__device__ unsigned g_bar_phase;    // +1 per step

// ---------------------------------------------------------------------------
// helpers
// ---------------------------------------------------------------------------
__device__ __forceinline__ uint32_t smem_u32(const void* p) {
    uint32_t a;
    asm("{ .reg .u64 t; cvta.to.shared.u64 t, %1; cvt.u32.u64 %0, t; }"
        : "=r"(a) : "l"(p));
    return a;
}
__device__ __forceinline__ void cpa16(uint32_t sdst, const void* gp) {
    asm volatile("cp.async.cg.shared.global [%0], [%1], 16;\n"
                 :: "r"(sdst), "l"(gp) : "memory");
}
__device__ __forceinline__ void ldm4(uint32_t& r0, uint32_t& r1,
                                     uint32_t& r2, uint32_t& r3, uint32_t addr) {
    asm volatile("ldmatrix.sync.aligned.m8n8.x4.shared.b16 {%0,%1,%2,%3}, [%4];"
                 : "=r"(r0), "=r"(r1), "=r"(r2), "=r"(r3) : "r"(addr));
}
__device__ __forceinline__ void mma_bf16(float& d0, float& d1, float& d2, float& d3,
                                         uint32_t a0, uint32_t a1, uint32_t a2, uint32_t a3,
                                         uint32_t b0, uint32_t b1) {
    asm volatile(
        "mma.sync.aligned.m16n8k16.row.col.f32.bf16.bf16.f32 "
        "{%0,%1,%2,%3}, {%4,%5,%6,%7}, {%8,%9}, {%0,%1,%2,%3};"
        : "+f"(d0), "+f"(d1), "+f"(d2), "+f"(d3)
        : "r"(a0), "r"(a1), "r"(a2), "r"(a3), "r"(b0), "r"(b1));
}

// ---------------------------------------------------------------------------
// fp32 -> bf16 hi/lo split (vectorized, once)
// ---------------------------------------------------------------------------
__global__ void split_kernel(const float* __restrict__ src,
                             __nv_bfloat16* __restrict__ hi,
                             __nv_bfloat16* __restrict__ lo)
{
    size_t i = (size_t)blockIdx.x * blockDim.x + threadIdx.x;   // float4 index
    float4 v = ((const float4*)src)[i];
    float f[4] = {v.x, v.y, v.z, v.w};
    __nv_bfloat16 h[4], l[4];
    #pragma unroll
    for (int q = 0; q < 4; q++) {
        h[q] = __float2bfloat16(f[q]);
        l[q] = __float2bfloat16(f[q] - __bfloat162float(h[q]));
    }
    ((uint2*)hi)[i] = *(uint2*)h;
    ((uint2*)lo)[i] = *(uint2*)l;
}

// h0 fp32 [b][j] -> bf16 hi/lo into ping buffer 0
__global__ void h0_prep_kernel(const float* __restrict__ h0,
                               __nv_bfloat16* __restrict__ hhi,
                               __nv_bfloat16* __restrict__ hlo)
{
    int idx = blockIdx.x * blockDim.x + threadIdx.x;
    float v = h0[idx];
    __nv_bfloat16 hi = __float2bfloat16(v);
    hhi[idx] = hi;
    hlo[idx] = __float2bfloat16(v - __bfloat162float(hi));
}

// no-op: aligns the harness's ncu skip window onto the scan kernel
__global__ void nop_kernel() {}

// ---------------------------------------------------------------------------
// Kernel 1: x_gates = inputs @ W_ih^T + bias_ih on tensor cores (proven R10)
// ---------------------------------------------------------------------------
#define XROWB 80u
#define XHALF (128u * XROWB)
#define XBUF  (4u * XHALF)
#define XGEMM_SMEM (2u * XBUF)

extern __shared__ char xsmem[];

__global__ __launch_bounds__(256) void xgemm_mma_kernel(
    const __nv_bfloat16* __restrict__ Ahi,
    const __nv_bfloat16* __restrict__ Alo,
    const __nv_bfloat16* __restrict__ Whi,
    const __nv_bfloat16* __restrict__ Wlo,
    const float* __restrict__ bias,
    float* __restrict__ xg)
{
    const uint32_t sb = smem_u32(xsmem);
    const int t    = threadIdx.x;
    const int wid  = t >> 5;
    const int lane = t & 31;
    const int m0   = blockIdx.y * 128;
    const int n0   = blockIdx.x * 128;
    const int wm   = (wid >> 2) * 64;
    const int wn   = (wid & 3) * 32;

    const int sub = lane >> 3;
    const uint32_t a_lane_off =
        (uint32_t)(((lane & 7) + ((sub & 1) << 3)) * XROWB + ((sub >> 1) << 4));
    const int bg   = lane >> 2;
    const int btid = lane & 3;

    float acc[4][4][4] = {};

    auto stage = [&](int w, int buf) {
        #pragma unroll
        for (int i = 0; i < 8; i++) {
            int c   = t + 256 * i;
            int op  = c >> 9;
            int rem = c & 511;
            int row = rem >> 2;
            int q   = rem & 3;
            const __nv_bfloat16* src;
            if (op == 0)      src = Ahi + (size_t)(m0 + row) * Isz + w * 32 + q * 8;
            else if (op == 1) src = Alo + (size_t)(m0 + row) * Isz + w * 32 + q * 8;
            else if (op == 2) src = Whi + (size_t)(n0 + row) * Isz + w * 32 + q * 8;
            else              src = Wlo + (size_t)(n0 + row) * Isz + w * 32 + q * 8;
            cpa16(sb + (uint32_t)buf * XBUF + (uint32_t)op * XHALF
                     + (uint32_t)(row * XROWB + q * 16), src);
        }
        asm volatile("cp.async.commit_group;\n" ::: "memory");
    };

    stage(0, 0);

    #pragma unroll 1
    for (int w = 0; w < 16; w++) {
        if (w < 15) {
            stage(w + 1, (w + 1) & 1);
            asm volatile("cp.async.wait_group 1;\n" ::: "memory");
        } else {
            asm volatile("cp.async.wait_group 0;\n" ::: "memory");
        }
        __syncthreads();

        const uint32_t bufb = sb + (uint32_t)(w & 1) * XBUF;
        const uint32_t* bhi_row[4];
        const uint32_t* blo_row[4];
        #pragma unroll
        for (int ni = 0; ni < 4; ni++) {
            uint32_t r = (uint32_t)((wn + ni * 8 + bg) * XROWB);
            bhi_row[ni] = (const uint32_t*)(xsmem + (w & 1) * XBUF + 2 * XHALF + r);
            blo_row[ni] = (const uint32_t*)(xsmem + (w & 1) * XBUF + 3 * XHALF + r);
        }

        #pragma unroll
        for (int kt = 0; kt < 2; kt++) {
            uint32_t bh0[4], bh1[4], bl0[4], bl1[4];
            #pragma unroll
            for (int ni = 0; ni < 4; ni++) {
                int kw = kt * 8 + btid;
                bh0[ni] = bhi_row[ni][kw];
                bh1[ni] = bhi_row[ni][kw + 4];
                bl0[ni] = blo_row[ni][kw];
                bl1[ni] = blo_row[ni][kw + 4];
            }
            #pragma unroll
            for (int mi = 0; mi < 4; mi++) {
                uint32_t abase = bufb + a_lane_off
                               + (uint32_t)((wm + mi * 16) * XROWB + kt * 32);
                uint32_t ah0, ah1, ah2, ah3, al0, al1, al2, al3;
                ldm4(ah0, ah1, ah2, ah3, abase);
                ldm4(al0, al1, al2, al3, abase + XHALF);
                #pragma unroll
                for (int ni = 0; ni < 4; ni++) {
                    float* d = acc[mi][ni];
                    mma_bf16(d[0], d[1], d[2], d[3], ah0, ah1, ah2, ah3, bh0[ni], bh1[ni]);
                    mma_bf16(d[0], d[1], d[2], d[3], ah0, ah1, ah2, ah3, bl0[ni], bl1[ni]);
                    mma_bf16(d[0], d[1], d[2], d[3], al0, al1, al2, al3, bh0[ni], bh1[ni]);
                }
            }
        }
        __syncthreads();
    }

    #pragma unroll
    for (int ni = 0; ni < 4; ni++) {
        int nn = n0 + wn + ni * 8 + 2 * (lane & 3);
        float b0 = bias[nn], b1 = bias[nn + 1];
        #pragma unroll
        for (int mi = 0; mi < 4; mi++) {
            const float* d = acc[mi][ni];
            int m = m0 + wm + mi * 16 + (lane >> 2);
            int s = m & (Sq - 1), b = m >> 9;
            *(float2*)(xg + (size_t)s * (Bsz * G3) + (size_t)b * G3 + nn) =
                make_float2(d[0] + b0, d[1] + b1);
            int m2 = m + 8;
            int s2 = m2 & (Sq - 1), b2 = m2 >> 9;
            *(float2*)(xg + (size_t)s2 * (Bsz * G3) + (size_t)b2 * G3 + nn) =
                make_float2(d[2] + b0, d[3] + b1);
        }
    }
}

// ---------------------------------------------------------------------------
// Kernel 2: PERSISTENT bf16-split mma.sync GRU scan (R10 protocol).
// Deltas vs R10: triple-buffered h windows (1 sync/window instead of 2),
// two-level grid barrier (8 sub-counters + root, monotonic).
// ---------------------------------------------------------------------------
#define OFF_D   0u
#define OFF_W   8192u
#define WROWB   2064u
#define OFF_WLO (OFF_W + 24u * WROWB)
#define OFF_H   107520u
#define HROWB   272u
#define HHALF   (64u * HROWB)
#define HBUF    (2u * HHALF)
#define SCAN_SMEM (OFF_H + 3u * HBUF)     // 211,968 B (3-deep window ring)

extern __shared__ char smem_raw[];

__global__ __launch_bounds__(512, 1) void gru_scan_kernel(
    const float* __restrict__ xg,
    const float* __restrict__ Whh,
    const float* __restrict__ bhh,
    __nv_bfloat16* __restrict__ hb,
    float* __restrict__ out)
{
    const uint32_t sb = smem_u32(smem_raw);
    const int t    = threadIdx.x;
    const int wid  = t >> 5;
    const int lane = t & 31;
    const int j0   = blockIdx.x * 8;

    // ---- W -> smem as bf16 hi/lo (once) ----
    #pragma unroll
    for (int i = 0; i < 48; i++) {
        int idx = t + 512 * i;
        int r = idx >> 10;
        int k = idx & 1023;
        int gate = r >> 3, jr = r & 7;
        float v = Whh[(size_t)(gate * Hsz + j0 + jr) * Hsz + k];
        __nv_bfloat16 hi = __float2bfloat16(v);
        __nv_bfloat16 lo = __float2bfloat16(v - __bfloat162float(hi));
        *(__nv_bfloat16*)(smem_raw + OFF_W   + r * WROWB + k * 2) = hi;
        *(__nv_bfloat16*)(smem_raw + OFF_WLO + r * WROWB + k * 2) = lo;
    }
    __syncthreads();

    unsigned base = 0;
    if (t == 0) base = *(volatile unsigned*)&g_bar_phase;

    const int nt = wid >> 2;
    const int mt = wid & 3;
    const int sub   = lane >> 3;
    const int a_row = mt * 16 + (lane & 7) + ((sub & 1) << 3);
    const uint32_t a_off = (uint32_t)(a_row * HROWB + ((sub >> 1) << 4));
    const int bg   = lane >> 2;
    const int btid = lane & 3;
    const uint32_t* whi_p = (const uint32_t*)(smem_raw + OFF_W   + (nt * 8 + bg) * WROWB);
    const uint32_t* wlo_p = (const uint32_t*)(smem_raw + OFF_WLO + (nt * 8 + bg) * WROWB);

    float bhr[8], bhz[8], bhn[8];
    if (t < 64) {
        #pragma unroll
        for (int jj = 0; jj < 8; jj++) {
            bhr[jj] = bhh[j0 + jj];
            bhz[jj] = bhh[Hsz + j0 + jj];
            bhn[jj] = bhh[2 * Hsz + j0 + jj];
        }
    }

    float* Dp = (float*)(smem_raw + OFF_D);

    for (int s = 0; s < Sq; s++) {
        const int pin  = s & 1, pout = (s + 1) & 1;
        const __nv_bfloat16* hin_hi = hb + (size_t)pin * 2 * (Bsz * Hsz);
        const __nv_bfloat16* hin_lo = hin_hi + (Bsz * Hsz);
        __nv_bfloat16* hout_hi = hb + (size_t)pout * 2 * (Bsz * Hsz);
        __nv_bfloat16* hout_lo = hout_hi + (Bsz * Hsz);
        const float* xgs = xg + (size_t)s * (Bsz * G3);

        float xr[8], xz[8], xn[8], hp[8];
        if (t < 64) {
            const float* xb = xgs + (size_t)t * G3 + j0;
            float4 v0 = __ldg((const float4*)xb);
            float4 v1 = __ldg((const float4*)(xb + 4));
            xr[0]=v0.x; xr[1]=v0.y; xr[2]=v0.z; xr[3]=v0.w;
            xr[4]=v1.x; xr[5]=v1.y; xr[6]=v1.z; xr[7]=v1.w;
            v0 = __ldg((const float4*)(xb + Hsz));
            v1 = __ldg((const float4*)(xb + Hsz + 4));
            xz[0]=v0.x; xz[1]=v0.y; xz[2]=v0.z; xz[3]=v0.w;
            xz[4]=v1.x; xz[5]=v1.y; xz[6]=v1.z; xz[7]=v1.w;
            v0 = __ldg((const float4*)(xb + 2 * Hsz));
            v1 = __ldg((const float4*)(xb + 2 * Hsz + 4));
            xn[0]=v0.x; xn[1]=v0.y; xn[2]=v0.z; xn[3]=v0.w;
            xn[4]=v1.x; xn[5]=v1.y; xn[6]=v1.z; xn[7]=v1.w;
            // h_prev slice (t, j0..j0+8): produced by THIS block last step
            uint4 uh = __ldcg((const uint4*)(hin_hi + (size_t)t * Hsz + j0));
            uint4 ul = __ldcg((const uint4*)(hin_lo + (size_t)t * Hsz + j0));
            const __nv_bfloat16* ph = (const __nv_bfloat16*)&uh;
            const __nv_bfloat16* pl = (const __nv_bfloat16*)&ul;
            #pragma unroll
            for (int jj = 0; jj < 8; jj++)
                hp[jj] = __bfloat162float(ph[jj]) + __bfloat162float(pl[jj]);
        }

        float dA[4] = {}, dB[4] = {};

        // stage window w into ring buffer w%3
        auto stage = [&](int w) {
            int buf = w % 3;
            #pragma unroll
            for (int i = 0; i < 4; i++) {
                int c    = t + 512 * i;
                int half = c >> 10;
                int rem  = c & 1023;
                int row  = rem >> 4;
                int cq   = rem & 15;
                const char* src = (const char*)(half ? hin_lo : hin_hi)
                                  + row * 2048 + w * 256 + cq * 16;
                cpa16(sb + OFF_H + (uint32_t)buf * HBUF + half * HHALF
                         + row * HROWB + cq * 16, src);
            }
            asm volatile("cp.async.commit_group;\n" ::: "memory");
        };

        stage(0);
        stage(1);

        #pragma unroll 1
        for (int w = 0; w < 8; w++) {
            if (w < 7) asm volatile("cp.async.wait_group 1;\n" ::: "memory");
            else       asm volatile("cp.async.wait_group 0;\n" ::: "memory");
            __syncthreads();   // window w data in; all warps done with iter w-1

            if (wid < 12) {
                const uint32_t abase = sb + OFF_H + (uint32_t)(w % 3) * HBUF + a_off;
                #pragma unroll
                for (int kt = 0; kt < 8; kt++) {
                    float* d = (kt & 1) ? dB : dA;
                    uint32_t ah0, ah1, ah2, ah3, al0, al1, al2, al3;
                    ldm4(ah0, ah1, ah2, ah3, abase + kt * 32);
                    ldm4(al0, al1, al2, al3, abase + HHALF + kt * 32);
                    int kw = (w * 8 + kt) * 8 + btid;
                    uint32_t bh0 = whi_p[kw], bh1 = whi_p[kw + 4];
                    uint32_t bl0 = wlo_p[kw], bl1 = wlo_p[kw + 4];
                    mma_bf16(d[0], d[1], d[2], d[3], ah0, ah1, ah2, ah3, bh0, bh1);
                    mma_bf16(d[0], d[1], d[2], d[3], ah0, ah1, ah2, ah3, bl0, bl1);
                    mma_bf16(d[0], d[1], d[2], d[3], al0, al1, al2, al3, bh0, bh1);
                }
            }
            // prefetch window w+2 (writes buf (w+2)%3 == (w-1)%3: free now)
            if (w + 2 < 8) stage(w + 2);
        }

        if (wid < 12) {
            int m  = mt * 16 + (lane >> 2);
            int nc = nt * 8 + 2 * (lane & 3);
            Dp[m * 26 + nc]           = dA[0] + dB[0];
            Dp[m * 26 + nc + 1]       = dA[1] + dB[1];
            Dp[(m + 8) * 26 + nc]     = dA[2] + dB[2];
            Dp[(m + 8) * 26 + nc + 1] = dA[3] + dB[3];
        }
        __syncthreads();

        if (t < 64) {
            __nv_bfloat16 whi[8], wlo[8];
            float hnv[8];
            #pragma unroll
            for (int jj = 0; jj < 8; jj++) {
                float ar = Dp[t * 26 + jj];
                float az = Dp[t * 26 + 8 + jj];
                float an = Dp[t * 26 + 16 + jj];
                float r = 1.f / (1.f + expf(-(xr[jj] + ar + bhr[jj])));
                float z = 1.f / (1.f + expf(-(xz[jj] + az + bhz[jj])));
                float n = tanhf(xn[jj] + r * (an + bhn[jj]));
                float h = (1.f - z) * n + z * hp[jj];
                hnv[jj] = h;
                __nv_bfloat16 hi = __float2bfloat16(h);
                whi[jj] = hi;
                wlo[jj] = __float2bfloat16(h - __bfloat162float(hi));
            }
            float* op = out + (size_t)t * Sq * Hsz + (size_t)s * Hsz + j0;
            *(float4*)op       = make_float4(hnv[0], hnv[1], hnv[2], hnv[3]);
            *(float4*)(op + 4) = make_float4(hnv[4], hnv[5], hnv[6], hnv[7]);
            *(uint4*)(hout_hi + (size_t)t * Hsz + j0) = *(uint4*)whi;
            *(uint4*)(hout_lo + (size_t)t * Hsz + j0) = *(uint4*)wlo;
            if (s == Sq - 1) {
                float* hn = out + (size_t)Bsz * Sq * Hsz + (size_t)t * Hsz + j0;
                *(float4*)hn       = make_float4(hnv[0], hnv[1], hnv[2], hnv[3]);
                *(float4*)(hn + 4) = make_float4(hnv[4], hnv[5], hnv[6], hnv[7]);
            }
            __threadfence();   // release this block's h slice (device scope)
        }

        // ---- two-level grid barrier between steps ----
        __syncthreads();
        if (t == 0 && s + 1 < Sq) {
            __threadfence();
            unsigned a = atomicAdd(&g_sub[blockIdx.x & 7].v, 1u);
            bool last = false;
            if ((a & 15u) == 15u) {                       // 16th arrival here
                unsigned r = atomicAdd(&g_root, 1u);
                if ((r & 7u) == 7u) {                     // 8th sub-group
                    __threadfence();
                    atomicAdd(&g_bar_phase, 1u);
                    last = true;
                }
            }
            if (!last) {
                unsigned target = (unsigned)(s + 1);
                unsigned spins = 0;
                while ((unsigned)(*(volatile unsigned*)&g_bar_phase - base) < target) {
                    if (++spins > 200000000u) break;      // fail loud, not hung
                }
                __threadfence();
            }
        }
        __syncthreads();
    }
}

// ---------------------------------------------------------------------------
// kernel_launch (graph-capturable: kernel launches only)
// ---------------------------------------------------------------------------
extern "C" void kernel_launch(void* const* d_in, const int* in_sizes, int n_in,
                              void* d_out, int out_size)
{
    const float* inputs = (const float*)d_in[0];
    const float* h0     = (const float*)d_in[1];
    const float* Wih    = (const float*)d_in[2];
    const float* Whh    = (const float*)d_in[3];
    const float* bih    = (const float*)d_in[4];
    const float* bhh    = (const float*)d_in[5];
    float* out = (float*)d_out;

    float* xg = nullptr;
    __nv_bfloat16 *hb = nullptr, *ahi = nullptr, *alo = nullptr,
                  *whi = nullptr, *wlo = nullptr;
    cudaGetSymbolAddress((void**)&xg,  g_xg);
    cudaGetSymbolAddress((void**)&hb,  g_hb);
    cudaGetSymbolAddress((void**)&ahi, g_Ahi);
    cudaGetSymbolAddress((void**)&alo, g_Alo);
    cudaGetSymbolAddress((void**)&whi, g_Whi);
    cudaGetSymbolAddress((void**)&wlo, g_Wlo);

    cudaFuncSetAttribute(gru_scan_kernel,
                         cudaFuncAttributeMaxDynamicSharedMemorySize, SCAN_SMEM);
    cudaFuncSetAttribute(xgemm_mma_kernel,
                         cudaFuncAttributeMaxDynamicSharedMemorySize, XGEMM_SMEM);

    // Phase A: split inputs/Wih to bf16 hi/lo, then HMMA input-projection GEMM
    split_kernel<<<(int)((size_t)Bsz * Sq * Isz / 4 / 256), 256>>>(inputs, ahi, alo);
    split_kernel<<<(int)((size_t)G3 * Isz / 4 / 256), 256>>>(Wih, whi, wlo);
    h0_prep_kernel<<<(Bsz * Hsz) / 256, 256>>>(h0, hb, hb + Bsz * Hsz);

    dim3 ggrid(G3 / 128, (Bsz * Sq) / 128);   // (24, 256)
    xgemm_mma_kernel<<<ggrid, 256, XGEMM_SMEM>>>(ahi, alo, whi, wlo, bih, xg);

    // profiling alignment: makes the scan the 6th kernel launch
    nop_kernel<<<1, 32>>>();

    // Phase B: whole scan in ONE persistent kernel (two-level barrier)
    gru_scan_kernel<<<128, 512, SCAN_SMEM>>>(xg, Whh, bhh, hb, out);
}

// round 14
// speedup vs baseline: 1.1637x; 1.0840x over previous
#include <cuda_runtime.h>
#include <cuda_bf16.h>
#include <cstddef>
#include <cstdint>

#define Bsz 64
#define Sq  512
#define Isz 512
#define Hsz 1024
#define G3  3072   // 3*Hsz

// Scratch (static device allocations; no cudaMalloc anywhere)
__device__ float g_xg[(size_t)Sq * Bsz * G3];            // x_gates [s][b][g]
__device__ float g_h[2][Bsz * Hsz];                      // h ping-pong [ping][b][j] (tf32-valid fp32)
__device__ float g_Atf[(size_t)Bsz * Sq * Isz];          // inputs as tf32 [m][k]
__device__ float g_Wtf[(size_t)G3 * Isz];                // Wih as tf32 [n][k]

// two-level grid barrier (monotonic counters: no reset, graph-replay safe)
struct PadCtr { unsigned v; unsigned pad[31]; };
__device__ PadCtr  g_sub[8];        // 16 arrivals each per step
__device__ unsigned g_root;         // 8 arrivals per step
__device__ unsigned g_bar_phase;    // +1 per step

// ---------------------------------------------------------------------------
// helpers
// ---------------------------------------------------------------------------
__device__ __forceinline__ uint32_t smem_u32(const void* p) {
    uint32_t a;
    asm("{ .reg .u64 t; cvta.to.shared.u64 t, %1; cvt.u32.u64 %0, t; }"
        : "=r"(a) : "l"(p));
    return a;
}
__device__ __forceinline__ void cpa16(uint32_t sdst, const void* gp) {
    asm volatile("cp.async.cg.shared.global [%0], [%1], 16;\n"
                 :: "r"(sdst), "l"(gp) : "memory");
}
__device__ __forceinline__ void ldm4(uint32_t& r0, uint32_t& r1,
                                     uint32_t& r2, uint32_t& r3, uint32_t addr) {
    asm volatile("ldmatrix.sync.aligned.m8n8.x4.shared.b16 {%0,%1,%2,%3}, [%4];"
                 : "=r"(r0), "=r"(r1), "=r"(r2), "=r"(r3) : "r"(addr));
}
// single-chain TF32 MMA: m16n8k8 (base ISA sm_80+)
__device__ __forceinline__ void mma_tf32(float& d0, float& d1, float& d2, float& d3,
                                         uint32_t a0, uint32_t a1, uint32_t a2, uint32_t a3,
                                         uint32_t b0, uint32_t b1) {
    asm volatile(
        "mma.sync.aligned.m16n8k8.row.col.f32.tf32.tf32.f32 "
        "{%0,%1,%2,%3}, {%4,%5,%6,%7}, {%8,%9}, {%0,%1,%2,%3};"
        : "+f"(d0), "+f"(d1), "+f"(d2), "+f"(d3)
        : "r"(a0), "r"(a1), "r"(a2), "r"(a3), "r"(b0), "r"(b1));
}
__device__ __forceinline__ uint32_t f2tf32(float f) {
    uint32_t r;
    asm("cvt.rna.tf32.f32 %0, %1;" : "=r"(r) : "f"(f));
    return r;
}

// ---------------------------------------------------------------------------
// fp32 -> tf32-valid fp32 (round-to-nearest into tf32 grid), vectorized, once
// ---------------------------------------------------------------------------
__global__ void tf32_cvt_kernel(const float* __restrict__ src,
                                float* __restrict__ dst)
{
    size_t i = (size_t)blockIdx.x * blockDim.x + threadIdx.x;   // float4 index
    float4 v = ((const float4*)src)[i];
    uint4 o;
    o.x = f2tf32(v.x); o.y = f2tf32(v.y); o.z = f2tf32(v.z); o.w = f2tf32(v.w);
    ((uint4*)dst)[i] = o;
}

// h0 fp32 [b][j] -> tf32-valid fp32 into ping buffer 0
__global__ void h0_prep_kernel(const float* __restrict__ h0,
                               float* __restrict__ hdst)
{
    int idx = blockIdx.x * blockDim.x + threadIdx.x;
    ((uint32_t*)hdst)[idx] = f2tf32(h0[idx]);
}

// ---------------------------------------------------------------------------
// Kernel 1: x_gates = inputs @ W_ih^T + bias_ih, single-chain TF32 HMMA.
// Block 128m x 128n, 8 warps (2m x 4n), warp tile m64 x n32.
// K=512 in 16 windows of 32 fp32, double-buffered cp.async.
// ---------------------------------------------------------------------------
#define XROWB 144u                      // 32 fp32 = 128B + 16 pad
#define XHALF (128u * XROWB)            // 18432 B per operand per window
#define XBUF  (2u * XHALF)              // A,B = 36864 B
#define XGEMM_SMEM (2u * XBUF)          // 73728 B

extern __shared__ char xsmem[];

__global__ __launch_bounds__(256) void xgemm_mma_kernel(
    const float* __restrict__ Atf,
    const float* __restrict__ Wtf,
    const float* __restrict__ bias,
    float* __restrict__ xg)
{
    const uint32_t sb = smem_u32(xsmem);
    const int t    = threadIdx.x;
    const int wid  = t >> 5;
    const int lane = t & 31;
    const int m0   = blockIdx.y * 128;
    const int n0   = blockIdx.x * 128;
    const int wm   = (wid >> 2) * 64;
    const int wn   = (wid & 3) * 32;

    const int sub = lane >> 3;
    const uint32_t a_lane_off =
        (uint32_t)(((lane & 7) + ((sub & 1) << 3)) * XROWB + ((sub >> 1) << 4));
    const int bg   = lane >> 2;        // n within 8
    const int btid = lane & 3;         // k within 4

    float acc[4][4][4] = {};

    // staging: 2048 cp16 per window, 8 per thread
    auto stage = [&](int w, int buf) {
        #pragma unroll
        for (int i = 0; i < 8; i++) {
            int c   = t + 256 * i;          // 0..2047
            int op  = c >> 10;              // 0:A 1:B
            int rem = c & 1023;
            int row = rem >> 3;
            int q   = rem & 7;
            const float* src = (op ? Wtf + (size_t)(n0 + row) * Isz
                                   : Atf + (size_t)(m0 + row) * Isz)
                               + w * 32 + q * 4;
            cpa16(sb + (uint32_t)buf * XBUF + (uint32_t)op * XHALF
                     + (uint32_t)(row * XROWB + q * 16), src);
        }
        asm volatile("cp.async.commit_group;\n" ::: "memory");
    };

    stage(0, 0);

    #pragma unroll 1
    for (int w = 0; w < 16; w++) {
        if (w < 15) {
            stage(w + 1, (w + 1) & 1);
            asm volatile("cp.async.wait_group 1;\n" ::: "memory");
        } else {
            asm volatile("cp.async.wait_group 0;\n" ::: "memory");
        }
        __syncthreads();

        const uint32_t bufb = sb + (uint32_t)(w & 1) * XBUF;
        const uint32_t* brow[4];
        #pragma unroll
        for (int ni = 0; ni < 4; ni++)
            brow[ni] = (const uint32_t*)(xsmem + (w & 1) * XBUF + XHALF
                                         + (wn + ni * 8 + bg) * XROWB);

        #pragma unroll
        for (int kt = 0; kt < 4; kt++) {      // 4 k8-steps per 32-col window
            uint32_t b0[4], b1[4];
            #pragma unroll
            for (int ni = 0; ni < 4; ni++) {
                b0[ni] = brow[ni][kt * 8 + btid];
                b1[ni] = brow[ni][kt * 8 + btid + 4];
            }
            #pragma unroll
            for (int mi = 0; mi < 4; mi++) {
                uint32_t abase = bufb + a_lane_off
                               + (uint32_t)((wm + mi * 16) * XROWB + kt * 32);
                uint32_t a0, a1, a2, a3;
                ldm4(a0, a1, a2, a3, abase);
                #pragma unroll
                for (int ni = 0; ni < 4; ni++) {
                    float* d = acc[mi][ni];
                    mma_tf32(d[0], d[1], d[2], d[3], a0, a1, a2, a3, b0[ni], b1[ni]);
                }
            }
        }
        __syncthreads();
    }

    // ---- epilogue: add bias, scatter [m][n] -> xg[s][b][n] ----
    #pragma unroll
    for (int ni = 0; ni < 4; ni++) {
        int nn = n0 + wn + ni * 8 + 2 * (lane & 3);
        float b0 = bias[nn], b1 = bias[nn + 1];
        #pragma unroll
        for (int mi = 0; mi < 4; mi++) {
            const float* d = acc[mi][ni];
            int m = m0 + wm + mi * 16 + (lane >> 2);
            int s = m & (Sq - 1), b = m >> 9;
            *(float2*)(xg + (size_t)s * (Bsz * G3) + (size_t)b * G3 + nn) =
                make_float2(d[0] + b0, d[1] + b1);
            int m2 = m + 8;
            int s2 = m2 & (Sq - 1), b2 = m2 >> 9;
            *(float2*)(xg + (size_t)s2 * (Bsz * G3) + (size_t)b2 * G3 + nn) =
                make_float2(d[2] + b0, d[3] + b1);
        }
    }
}

// ---------------------------------------------------------------------------
// Kernel 2: PERSISTENT single-chain TF32 mma.sync GRU scan (R13 skeleton:
// triple-buffered h windows, 1 sync/window, two-level grid barrier).
// Block owns N=24 cols (8 j x 3 gates); W (tf32 fp32) in smem once.
// Per window (128 k): 16 k8-steps, 16 ldmatrix + 32 LDS + 16 MMA per warp.
// ---------------------------------------------------------------------------
#define OFF_D   0u                       // 64 x 26 fp32 = 6656 B
#define OFF_W   8192u
#define WROWB   4112u                    // 1024 fp32 = 4096B + 16 pad
#define OFF_H   (OFF_W + 24u * WROWB)    // 106880
#define HROWB   528u                     // 128 fp32 = 512B + 16 pad
#define HBUF    (64u * HROWB)            // 33792
#define SCAN_SMEM (OFF_H + 3u * HBUF)    // 208256 B

extern __shared__ char smem_raw[];

__global__ __launch_bounds__(512, 1) void gru_scan_kernel(
    const float* __restrict__ xg,
    const float* __restrict__ Whh,
    const float* __restrict__ bhh,
    float* __restrict__ hbuf,            // g_h base: [2][B*H]
    float* __restrict__ out)
{
    const uint32_t sb = smem_u32(smem_raw);
    const int t    = threadIdx.x;
    const int wid  = t >> 5;
    const int lane = t & 31;
    const int j0   = blockIdx.x * 8;

    // ---- W -> smem as tf32-valid fp32 (once) ----
    #pragma unroll
    for (int i = 0; i < 48; i++) {
        int idx = t + 512 * i;            // 0..24575
        int r = idx >> 10;                // 0..23 = gate*8 + jr
        int k = idx & 1023;
        int gate = r >> 3, jr = r & 7;
        float v = Whh[(size_t)(gate * Hsz + j0 + jr) * Hsz + k];
        *(uint32_t*)(smem_raw + OFF_W + r * WROWB + k * 4) = f2tf32(v);
    }
    __syncthreads();

    unsigned base = 0;
    if (t == 0) base = *(volatile unsigned*)&g_bar_phase;

    const int nt = wid >> 2;              // 0..2 gate tile (warps 0-11 compute)
    const int mt = wid & 3;               // 0..3 batch tile
    const int sub   = lane >> 3;
    const int a_row = mt * 16 + (lane & 7) + ((sub & 1) << 3);
    const uint32_t a_off = (uint32_t)(a_row * HROWB + ((sub >> 1) << 4));
    const int bg   = lane >> 2;
    const int btid = lane & 3;
    const uint32_t* wrow_base =
        (const uint32_t*)(smem_raw + OFF_W + (nt * 8 + bg) * WROWB);

    float bhr[8], bhz[8], bhn[8];
    if (t < 64) {
        #pragma unroll
        for (int jj = 0; jj < 8; jj++) {
            bhr[jj] = bhh[j0 + jj];
            bhz[jj] = bhh[Hsz + j0 + jj];
            bhn[jj] = bhh[2 * Hsz + j0 + jj];
        }
    }

    float* Dp = (float*)(smem_raw + OFF_D);

    for (int s = 0; s < Sq; s++) {
        const int pin  = s & 1, pout = (s + 1) & 1;
        const float* hin  = hbuf + (size_t)pin  * (Bsz * Hsz);
        float*       hout = hbuf + (size_t)pout * (Bsz * Hsz);
        const float* xgs  = xg + (size_t)s * (Bsz * G3);

        float xr[8], xz[8], xn[8], hp[8];
        if (t < 64) {
            const float* xb = xgs + (size_t)t * G3 + j0;
            float4 v0 = __ldg((const float4*)xb);
            float4 v1 = __ldg((const float4*)(xb + 4));
            xr[0]=v0.x; xr[1]=v0.y; xr[2]=v0.z; xr[3]=v0.w;
            xr[4]=v1.x; xr[5]=v1.y; xr[6]=v1.z; xr[7]=v1.w;
            v0 = __ldg((const float4*)(xb + Hsz));
            v1 = __ldg((const float4*)(xb + Hsz + 4));
            xz[0]=v0.x; xz[1]=v0.y; xz[2]=v0.z; xz[3]=v0.w;
            xz[4]=v1.x; xz[5]=v1.y; xz[6]=v1.z; xz[7]=v1.w;
            v0 = __ldg((const float4*)(xb + 2 * Hsz));
            v1 = __ldg((const float4*)(xb + 2 * Hsz + 4));
            xn[0]=v0.x; xn[1]=v0.y; xn[2]=v0.z; xn[3]=v0.w;
            xn[4]=v1.x; xn[5]=v1.y; xn[6]=v1.z; xn[7]=v1.w;
            // h_prev slice (t, j0..j0+8): produced by THIS block last step
            float4 h0v = __ldcg((const float4*)(hin + (size_t)t * Hsz + j0));
            float4 h1v = __ldcg((const float4*)(hin + (size_t)t * Hsz + j0 + 4));
            hp[0]=h0v.x; hp[1]=h0v.y; hp[2]=h0v.z; hp[3]=h0v.w;
            hp[4]=h1v.x; hp[5]=h1v.y; hp[6]=h1v.z; hp[7]=h1v.w;
        }

        float dA[4] = {}, dB[4] = {};

        // stage window w (k in [128w,128w+128)) into ring buffer w%3
        auto stage = [&](int w) {
            int buf = w % 3;
            #pragma unroll
            for (int i = 0; i < 4; i++) {
                int c   = t + 512 * i;          // 0..2047 cp16 slots
                int row = c >> 5;               // batch row 0..63
                int cq  = c & 31;               // 16B chunk in 512B
                const char* src = (const char*)hin + (size_t)row * 4096
                                  + w * 512 + cq * 16;
                cpa16(sb + OFF_H + (uint32_t)buf * HBUF
                         + row * HROWB + cq * 16, src);
            }
            asm volatile("cp.async.commit_group;\n" ::: "memory");
        };

        stage(0);
        stage(1);

        #pragma unroll 1
        for (int w = 0; w < 8; w++) {
            if (w < 7) asm volatile("cp.async.wait_group 1;\n" ::: "memory");
            else       asm volatile("cp.async.wait_group 0;\n" ::: "memory");
            __syncthreads();   // window w data in; all warps done with iter w-1

            if (wid < 12) {
                const uint32_t abase = sb + OFF_H + (uint32_t)(w % 3) * HBUF + a_off;
                const uint32_t* wrow = wrow_base + w * 128;
                #pragma unroll
                for (int kt = 0; kt < 16; kt++) {   // 16 k8-steps per window
                    float* d = (kt & 1) ? dB : dA;
                    uint32_t a0, a1, a2, a3;
                    ldm4(a0, a1, a2, a3, abase + kt * 32);
                    uint32_t b0 = wrow[kt * 8 + btid];
                    uint32_t b1 = wrow[kt * 8 + btid + 4];
                    mma_tf32(d[0], d[1], d[2], d[3], a0, a1, a2, a3, b0, b1);
                }
            }
            // prefetch window w+2 (writes buf (w+2)%3 == (w-1)%3: free now)
            if (w + 2 < 8) stage(w + 2);
        }

        if (wid < 12) {
            int m  = mt * 16 + (lane >> 2);
            int nc = nt * 8 + 2 * (lane & 3);
            Dp[m * 26 + nc]           = dA[0] + dB[0];
            Dp[m * 26 + nc + 1]       = dA[1] + dB[1];
            Dp[(m + 8) * 26 + nc]     = dA[2] + dB[2];
            Dp[(m + 8) * 26 + nc + 1] = dA[3] + dB[3];
        }
        __syncthreads();

        if (t < 64) {
            float hnv[8];
            uint32_t ht[8];
            #pragma unroll
            for (int jj = 0; jj < 8; jj++) {
                float ar = Dp[t * 26 + jj];
                float az = Dp[t * 26 + 8 + jj];
                float an = Dp[t * 26 + 16 + jj];
                float r = 1.f / (1.f + expf(-(xr[jj] + ar + bhr[jj])));
                float z = 1.f / (1.f + expf(-(xz[jj] + az + bhz[jj])));
                float n = tanhf(xn[jj] + r * (an + bhn[jj]));
                float h = (1.f - z) * n + z * hp[jj];
                hnv[jj] = h;
                ht[jj]  = f2tf32(h);    // next step's MMA operand
            }
            float* op = out + (size_t)t * Sq * Hsz + (size_t)s * Hsz + j0;
            *(float4*)op       = make_float4(hnv[0], hnv[1], hnv[2], hnv[3]);
            *(float4*)(op + 4) = make_float4(hnv[4], hnv[5], hnv[6], hnv[7]);
            *(uint4*)(hout + (size_t)t * Hsz + j0)     = *(uint4*)ht;
            *(uint4*)(hout + (size_t)t * Hsz + j0 + 4) = *(uint4*)(ht + 4);
            if (s == Sq - 1) {
                float* hn = out + (size_t)Bsz * Sq * Hsz + (size_t)t * Hsz + j0;
                *(float4*)hn       = make_float4(hnv[0], hnv[1], hnv[2], hnv[3]);
                *(float4*)(hn + 4) = make_float4(hnv[4], hnv[5], hnv[6], hnv[7]);
            }
            __threadfence();   // release this block's h slice (device scope)
        }

        // ---- two-level grid barrier between steps ----
        __syncthreads();
        if (t == 0 && s + 1 < Sq) {
            __threadfence();
            unsigned a = atomicAdd(&g_sub[blockIdx.x & 7].v, 1u);
            bool last = false;
            if ((a & 15u) == 15u) {                       // 16th arrival here
                unsigned r = atomicAdd(&g_root, 1u);
                if ((r & 7u) == 7u) {                     // 8th sub-group
                    __threadfence();
                    atomicAdd(&g_bar_phase, 1u);
                    last = true;
                }
            }
            if (!last) {
                unsigned target = (unsigned)(s + 1);
                unsigned spins = 0;
                while ((unsigned)(*(volatile unsigned*)&g_bar_phase - base) < target) {
                    if (++spins > 200000000u) break;      // fail loud, not hung
                }
                __threadfence();
            }
        }
        __syncthreads();
    }
}

// ---------------------------------------------------------------------------
// kernel_launch (graph-capturable: kernel launches only)
// ---------------------------------------------------------------------------
extern "C" void kernel_launch(void* const* d_in, const int* in_sizes, int n_in,
                              void* d_out, int out_size)
{
    const float* inputs = (const float*)d_in[0];
    const float* h0     = (const float*)d_in[1];
    const float* Wih    = (const float*)d_in[2];
    const float* Whh    = (const float*)d_in[3];
    const float* bih    = (const float*)d_in[4];
    const float* bhh    = (const float*)d_in[5];
    float* out = (float*)d_out;

    float *xg = nullptr, *hb = nullptr, *atf = nullptr, *wtf = nullptr;
    cudaGetSymbolAddress((void**)&xg,  g_xg);
    cudaGetSymbolAddress((void**)&hb,  g_h);
    cudaGetSymbolAddress((void**)&atf, g_Atf);
    cudaGetSymbolAddress((void**)&wtf, g_Wtf);

    cudaFuncSetAttribute(gru_scan_kernel,
                         cudaFuncAttributeMaxDynamicSharedMemorySize, SCAN_SMEM);
    cudaFuncSetAttribute(xgemm_mma_kernel,
                         cudaFuncAttributeMaxDynamicSharedMemorySize, XGEMM_SMEM);

    // Phase A: convert inputs/Wih/h0 to tf32 grid, then TF32 input-projection GEMM
    tf32_cvt_kernel<<<(int)((size_t)Bsz * Sq * Isz / 4 / 256), 256>>>(inputs, atf);
    tf32_cvt_kernel<<<(int)((size_t)G3 * Isz / 4 / 256), 256>>>(Wih, wtf);
    h0_prep_kernel<<<(Bsz * Hsz) / 256, 256>>>(h0, hb);

    dim3 ggrid(G3 / 128, (Bsz * Sq) / 128);   // (24, 256)
    xgemm_mma_kernel<<<ggrid, 256, XGEMM_SMEM>>>(atf, wtf, bih, xg);

    // Phase B: whole scan in ONE persistent kernel (two-level barrier)
    gru_scan_kernel<<<128, 512, SCAN_SMEM>>>(xg, Whh, bhh, hb, out);
}